// round 17
// baseline (speedup 1.0000x reference)
#include <cuda_runtime.h>

// Shapes fixed by reference setup_inputs
#define NTOK   16384      // B*T
#define DDIM   2048
#define NEXP   16
#define TOK_W  8          // tokens per group
#define NGRP   (NTOK / TOK_W)          // 2048 groups
#define NASSIGN (NGRP * 2)             // 4096 warp assignments (group x d-half)
#define GRID_MAIN 148
#define BLOCK_MAIN 896
#define WARPS_CTA 28
#define NWIN   32         // 32-d x-windows per d-half
#define STAGES 3
#define STG_FLOATS 256    // 8 tok * 32 d = 1KB per stage

#define W2_U64      (NEXP * DDIM / 2)              // 16384 u64 = 128KB
#define XSTG_FLOATS (WARPS_CTA * STAGES * STG_FLOATS)   // 21504 floats = 84KB

__device__ float g_zp[GRID_MAIN];     // per-CTA z-loss partials (deterministic)
__device__ unsigned int g_ctr;        // last-CTA ticket (reset each launch)

typedef unsigned long long u64;

__device__ __forceinline__ float fnoise(float x) {
    return copysignf(sqrtf(fabsf(x)), x);
}
__device__ __forceinline__ void ffma2(u64 &d, u64 a, u64 b) {
    asm("fma.rn.f32x2 %0, %1, %2, %0;" : "+l"(d) : "l"(a), "l"(b));
}
__device__ __forceinline__ u64 addx2(u64 a, u64 b) {
    u64 r; asm("add.rn.f32x2 %0, %1, %2;" : "=l"(r) : "l"(a), "l"(b)); return r;
}
__device__ __forceinline__ u64 pack2(float lo, float hi) {
    u64 r; asm("mov.b64 %0, {%1, %2};" : "=l"(r) : "f"(lo), "f"(hi)); return r;
}
__device__ __forceinline__ float2 unpack64(u64 v) {
    float2 r; asm("mov.b64 {%0, %1}, %2;" : "=f"(r.x), "=f"(r.y) : "l"(v)); return r;
}
__device__ __forceinline__ unsigned smem_u32(const void* p) {
    return (unsigned)__cvta_generic_to_shared(p);
}
__device__ __forceinline__ void cp16(unsigned dst, const float* src) {
    asm volatile("cp.async.cg.shared.global [%0], [%1], 16;"
                 :: "r"(dst), "l"(src) : "memory");
}
__device__ __forceinline__ void cp_commit() {
    asm volatile("cp.async.commit_group;" ::: "memory");
}
__device__ __forceinline__ void cp_wait2() {
    asm volatile("cp.async.wait_group 2;" ::: "memory");
}
__device__ __forceinline__ void cp_wait0() {
    asm volatile("cp.async.wait_group 0;" ::: "memory");
}

// ---------------------------------------------------------------------------
// R16 D-split structure + FFMA2 via eighth-warp expert split.
//   Assignment a = blockIdx*28 + wid (a < 4096): group g = a>>1 (8 tokens),
//   d-half = a&1 (1024 d).  Partner warp = wid^1, same CTA.
//   Warp = 8 eighths (4 lanes); eighth q8 = lane>>2 owns experts 2q8, 2q8+1;
//   lane j4 = lane&3 owns d = subwin*16 + j4*4 .. +3.
//   acc[8 tok][2 exp] = packed f32x2 (even-d, odd-d) = 32 regs; ~62 total.
//   SMEM w (d-pair packed): u64 idx = wi16*128 + el*64 + lane*2 + k
//     (wi16 = d>>4, el = e&1, lane = (e>>1)*4 + ((d>>2)&3), k = (d>>1)&1)
//   -> per (16-d subwindow, el): ONE conflict-free LDS.128.
//   Mainloop has ZERO packing MOVs: x LDS.128 gives (x_d,x_{d+1}) u64 pairs.
//   x staged per warp via depth-3 cp.async over 32-d windows (1KB stages).
//   Epilogue: 4-lane butterfly, even+odd horiz add, publish 8x16 logits to
//   retired stage, __syncthreads, even warp combines halves, top-2/softmax,
//   fused last-CTA z-loss.
// ---------------------------------------------------------------------------
__global__ void __launch_bounds__(BLOCK_MAIN, 1)
router_kernel(const float* __restrict__ x,
              const float* __restrict__ w,  const float* __restrict__ sw,
              const float* __restrict__ b,  const float* __restrict__ sb,
              const float* __restrict__ ei, const float* __restrict__ eo,
              float* __restrict__ out) {
    extern __shared__ __align__(16) float smem_raw[];
    u64*   w2_s   = (u64*)smem_raw;                  // 128KB
    float* xstage = (float*)(w2_s + W2_U64);         // 84KB
    float* fi_s   = xstage + XSTG_FLOATS;            // 2048
    float* fo_s   = fi_s + DDIM;                     // 16
    float* b_s    = fo_s + NEXP;                     // 16
    float* z_s    = b_s + NEXP;                      // 28

    // --- noise factors ---
    for (int i = threadIdx.x; i < DDIM; i += BLOCK_MAIN) fi_s[i] = fnoise(ei[i]);
    if (threadIdx.x < NEXP) {
        float fo = fnoise(eo[threadIdx.x]);
        fo_s[threadIdx.x] = fo;
        b_s[threadIdx.x] = b[threadIdx.x] + sb[threadIdx.x] * fo;
    }
    __syncthreads();

    // --- noisy weights into [wi16][el][lane][k] d-pair-packed layout ---
    for (int it = threadIdx.x; it < NEXP * (DDIM / 2); it += BLOCK_MAIN) {
        int e = it >> 10;              // expert
        int d = (it & 1023) * 2;       // even d
        float2 wv = *(const float2*)(w  + e * DDIM + d);
        float2 sv = *(const float2*)(sw + e * DDIM + d);
        float2 fi = *(const float2*)(fi_s + d);
        float fo = fo_s[e];
        float a0 = wv.x + sv.x * fo * fi.x;
        float a1 = wv.y + sv.y * fo * fi.y;
        int wi16 = d >> 4, el = e & 1, k = (d >> 1) & 1;
        int ln = (e >> 1) * 4 + ((d >> 2) & 3);
        w2_s[wi16 * 128 + el * 64 + ln * 2 + k] = pack2(a0, a1);
    }
    __syncthreads();

    const int lane = threadIdx.x & 31;
    const int wid  = threadIdx.x >> 5;
    const int a    = blockIdx.x * WARPS_CTA + wid;   // assignment id
    const int j4   = lane & 3;                       // d-slot within subwindow
    const int q8   = lane >> 2;                      // eighth (2-expert group)
    const bool act = (a < NASSIGN);
    const int g    = a >> 1;                         // token group
    const int half = a & 1;                          // d half

    float* warp_stg = xstage + wid * (STAGES * STG_FLOATS);

    if (act) {
        const int t0 = g * TOK_W;
        const float* xg = x + (size_t)t0 * DDIM + half * 1024;
        unsigned stg_u32 = smem_u32(warp_stg);

        // prime 3 stages with windows 0..2  (stage: 64 16B-slots, slot=t*8+s4)
        #pragma unroll
        for (int s = 0; s < STAGES; s++) {
            #pragma unroll
            for (int tp = 0; tp < 2; tp++) {
                int slot = tp * 32 + lane;
                int t = slot >> 3, s4 = slot & 7;
                cp16(stg_u32 + s * 1024 + slot * 16,
                     xg + t * DDIM + s * 32 + s4 * 4);
            }
            cp_commit();
        }

        u64 acc[TOK_W][2];
        #pragma unroll
        for (int t = 0; t < TOK_W; t++) {
            acc[t][0] = 0ULL;
            acc[t][1] = 0ULL;
        }

        int stage = 0;
        #pragma unroll 1
        for (int wi = 0; wi < NWIN; wi++) {
            cp_wait2();   // window wi resident

            #pragma unroll
            for (int sub = 0; sub < 2; sub++) {
                // global 16-d window index
                const int wi16 = half * 64 + wi * 2 + sub;
                // w for this subwindow: 2 conflict-free LDS.128
                const u64* wb = w2_s + wi16 * 128 + lane * 2;
                ulonglong2 wv0 = *(const ulonglong2*)(wb);        // el=0
                ulonglong2 wv1 = *(const ulonglong2*)(wb + 64);   // el=1

                const float* xs = warp_stg + stage * STG_FLOATS
                                + sub * 16 + j4 * 4;
                #pragma unroll
                for (int t = 0; t < TOK_W; t++) {
                    ulonglong2 xu = *(const ulonglong2*)(xs + t * 32);
                    ffma2(acc[t][0], xu.x, wv0.x);
                    ffma2(acc[t][0], xu.y, wv0.y);
                    ffma2(acc[t][1], xu.x, wv1.x);
                    ffma2(acc[t][1], xu.y, wv1.y);
                }
            }

            // refill this stage with window wi+3
            if (wi < NWIN - STAGES) {
                #pragma unroll
                for (int tp = 0; tp < 2; tp++) {
                    int slot = tp * 32 + lane;
                    int t = slot >> 3, s4 = slot & 7;
                    cp16(stg_u32 + stage * 1024 + slot * 16,
                         xg + t * DDIM + (wi + 3) * 32 + s4 * 4);
                }
            }
            cp_commit();   // uniform commit keeps wait_group algebra exact
            stage = (stage == STAGES - 1) ? 0 : stage + 1;
        }
        cp_wait0();   // drain before reusing own stage as scratch

        // butterfly over the 4 j4-lanes within each eighth, then even+odd add
        float fs[TOK_W][2];
        #pragma unroll
        for (int t = 0; t < TOK_W; t++)
            #pragma unroll
            for (int el = 0; el < 2; el++) {
                u64 s = acc[t][el];
                s = addx2(s, __shfl_xor_sync(0xffffffffu, s, 2));
                s = addx2(s, __shfl_xor_sync(0xffffffffu, s, 1));
                float2 qv = unpack64(s);
                fs[t][el] = qv.x + qv.y;
            }

        // publish this half's 8x16 partial logits into own retired stage
        // red[t*16 + e]; eighth q8 writes its 2 experts per token
        if (j4 == 0) {
            #pragma unroll
            for (int t = 0; t < TOK_W; t++)
                *(float2*)(warp_stg + t * 16 + q8 * 2) =
                    make_float2(fs[t][0], fs[t][1]);
        }
    }

    __syncthreads();   // all halves published

    float zl = 0.0f;
    if (act && half == 0) {
        // combine with partner (wid+1, same CTA) and run epilogue
        const float* r0 = warp_stg;                                   // half 0
        const float* r1 = xstage + (wid + 1) * (STAGES * STG_FLOATS); // half 1

        const int town = lane >> 2;      // this lane's token (0..7)
        const int qq   = lane & 3;       // this lane's 4-expert output slice
        const int t0   = g * TOK_W;
        float* idx_out = out + (size_t)NTOK * NEXP;

        float v[NEXP];
        #pragma unroll
        for (int g2 = 0; g2 < 4; g2++) {
            float4 u0 = *(const float4*)(r0 + town * 16 + g2 * 4);
            float4 u1 = *(const float4*)(r1 + town * 16 + g2 * 4);
            v[g2 * 4 + 0] = u0.x + u1.x;
            v[g2 * 4 + 1] = u0.y + u1.y;
            v[g2 * 4 + 2] = u0.z + u1.z;
            v[g2 * 4 + 3] = u0.w + u1.w;
        }

        float m1 = -1e30f, m2 = -1e30f;
        int i1 = 0, i2 = 0;
        #pragma unroll
        for (int e = 0; e < NEXP; e++) {
            float le = v[e] + b_s[e];
            if (le > m1)      { m2 = m1; i2 = i1; m1 = le; i1 = e; }
            else if (le > m2) { m2 = le; i2 = e; }
        }
        float ez = __expf(m2 - m1);
        float rz = 1.0f / (1.0f + ez);
        float p1 = rz, p2 = ez * rz;

        const int tok = t0 + town;
        const int e0 = qq * 4;
        float4 o4;
        o4.x = (e0 + 0 == i1) ? p1 : ((e0 + 0 == i2) ? p2 : 0.0f);
        o4.y = (e0 + 1 == i1) ? p1 : ((e0 + 1 == i2) ? p2 : 0.0f);
        o4.z = (e0 + 2 == i1) ? p1 : ((e0 + 2 == i2) ? p2 : 0.0f);
        o4.w = (e0 + 3 == i1) ? p1 : ((e0 + 3 == i2) ? p2 : 0.0f);
        *(float4*)(out + (size_t)tok * NEXP + e0) = o4;
        if (qq == 0)
            *(float2*)(idx_out + (size_t)tok * 2) =
                make_float2((float)i1, (float)i2);

        float lse = m1 + log1pf(ez);
        zl = (qq == 0) ? lse * lse : 0.0f;
    }
    // warp-reduce z (inactive / odd warps contribute 0)
    #pragma unroll
    for (int k = 16; k > 0; k >>= 1)
        zl += __shfl_xor_sync(0xffffffffu, zl, k);
    if (lane == 0) z_s[wid] = zl;

    // --- fused z-loss reduction: CTA partial, then last CTA finishes ---
    __syncthreads();
    __shared__ unsigned int s_last;
    if (threadIdx.x == 0) {
        float acc_z = 0.0f;
        #pragma unroll
        for (int i = 0; i < WARPS_CTA; i++) acc_z += z_s[i];
        g_zp[blockIdx.x] = acc_z;
        __threadfence();
        unsigned int ticket = atomicAdd(&g_ctr, 1u);
        s_last = (ticket == GRID_MAIN - 1) ? 1u : 0u;
    }
    __syncthreads();
    if (s_last && wid == 0) {
        float acc_z = 0.0f;
        for (int i = lane; i < GRID_MAIN; i += 32) acc_z += __ldcg(&g_zp[i]);
        #pragma unroll
        for (int k = 16; k > 0; k >>= 1)
            acc_z += __shfl_xor_sync(0xffffffffu, acc_z, k);
        if (lane == 0) {
            out[(size_t)NTOK * NEXP + (size_t)NTOK * 2] = acc_z * (1.0f / (float)NTOK);
            g_ctr = 0;   // reset for next launch / graph replay
        }
    }
}

// ---------------------------------------------------------------------------
extern "C" void kernel_launch(void* const* d_in, const int* in_sizes, int n_in,
                              void* d_out, int out_size) {
    const float* x  = (const float*)d_in[0];  // mh_output [4,4096,2048]
    const float* w  = (const float*)d_in[1];  // weight [16,2048]
    const float* sw = (const float*)d_in[2];  // sigma_weight
    const float* b  = (const float*)d_in[3];  // bias [16]
    const float* sb = (const float*)d_in[4];  // sigma_bias
    const float* ei = (const float*)d_in[5];  // eps_in [2048]
    const float* eo = (const float*)d_in[6];  // eps_out [16]
    float* out = (float*)d_out;

    const size_t smem_bytes = (size_t)W2_U64 * 8
                            + (size_t)(XSTG_FLOATS + DDIM + 2 * NEXP + WARPS_CTA)
                              * sizeof(float)
                            + 64;
    cudaFuncSetAttribute(router_kernel,
                         cudaFuncAttributeMaxDynamicSharedMemorySize,
                         (int)smem_bytes);
    router_kernel<<<GRID_MAIN, BLOCK_MAIN, smem_bytes>>>(x, w, sw, b, sb, ei, eo, out);
}